// round 5
// baseline (speedup 1.0000x reference)
#include <cuda_runtime.h>
#include <cstdint>

#define C 19
#define CPAD 20
#define DF 256
#define NPIX_MAX 262144

// ---------------- scratch (device globals; no runtime allocation) ----------------
__device__ float g_sums[C * DF];
__device__ float g_denom[C];
__device__ int g_src_count;
__device__ uint2 g_desc_src[NPIX_MAX];   // {row<<5 | cls, bits(w=1)}
__device__ uint2 g_desc_tgt[NPIX_MAX];   // {row<<5 | cls, bits(1-conf)}
__device__ double g_total;
__device__ double g_ws;

typedef unsigned long long ull;

union F4U { float4 f; ulonglong2 u; };
union U2F { ull u; float2 f; };

__device__ __forceinline__ void fma2(ull& d, ull a, ull b) {
    asm("fma.rn.f32x2 %0, %1, %2, %0;" : "+l"(d) : "l"(a), "l"(b));
}

// ---------------- K0: zero scratch (must run every replay) ----------------
__global__ void k0_zero() {
    int t = threadIdx.x;
    for (int i = t; i < C * DF; i += 256) g_sums[i] = 0.f;
    if (t < C) g_denom[t] = 0.f;
    if (t == 0) { g_total = 0.0; g_ws = 0.0; g_src_count = 0; }
}

// ---------------- K1a: denoms + ws + entry descriptors ----------------
#define K1A_BLOCKS 512
__global__ void __launch_bounds__(256) k1a_meta(
    const float* __restrict__ conf, const int* __restrict__ sarg,
    const int* __restrict__ targ, const int* __restrict__ smask, int N)
{
    __shared__ float sden[C];
    __shared__ float swsum[8];
    const int t = threadIdx.x;
    if (t < C) sden[t] = 0.f;
    float wsl = 0.f;
    __syncthreads();

    const int stride = gridDim.x * blockDim.x;
    const int iters = (N + stride - 1) / stride;
    for (int it = 0; it < iters; it++) {
        int i = it * stride + blockIdx.x * blockDim.x + t;
        int flag = 0, cs = 0;
        if (i < N) {
            flag = (smask[i] != 0);
            cs = sarg[i];
            int ct = targ[i];
            float w = 1.f - conf[i];
            if (flag) { atomicAdd(&sden[cs], 1.f); wsl += 1.f; }
            atomicAdd(&sden[ct], w);
            g_desc_tgt[i] = make_uint2(((unsigned)i << 5) | (unsigned)ct, __float_as_uint(w));
        }
        unsigned bal = __ballot_sync(0xffffffffu, flag);
        int cnt = __popc(bal);
        int bbase = 0;
        if ((t & 31) == 0 && cnt) bbase = atomicAdd(&g_src_count, cnt);
        bbase = __shfl_sync(0xffffffffu, bbase, 0);
        if (flag) {
            int rank = __popc(bal & ((1u << (t & 31)) - 1u));
            g_desc_src[bbase + rank] = make_uint2(((unsigned)i << 5) | (unsigned)cs, __float_as_uint(1.f));
        }
    }

    __syncthreads();
    if (t < C) atomicAdd(&g_denom[t], sden[t]);
    #pragma unroll
    for (int o = 16; o; o >>= 1) wsl += __shfl_down_sync(0xffffffffu, wsl, o);
    if ((t & 31) == 0) swsum[t >> 5] = wsl;
    __syncthreads();
    if (t == 0) {
        float s = 0.f;
        #pragma unroll
        for (int w = 0; w < 8; w++) s += swsum[w];
        atomicAdd(&g_ws, (double)s);
    }
}

// ---------------- K1b: streaming per-class feature sums (SoA accumulators) -----
#define K1B_BLOCKS 740
__global__ void __launch_bounds__(256) k1b_sums(
    const float* __restrict__ sfeat, const float* __restrict__ tfeat, int N)
{
    __shared__ float accx[2][C * 128];   // [subgroup][cls*128 + l]
    __shared__ float accy[2][C * 128];
    const int t = threadIdx.x;
    const int sub = t >> 7;            // 0 or 1
    const int l = t & 127;             // dim pair owner: dims [2l, 2l+1]

    for (int i = t; i < 2 * C * 128; i += 256) { ((float*)accx)[i] = 0.f; ((float*)accy)[i] = 0.f; }
    __syncthreads();

    const int M = g_src_count;
    const int E = M + N;
    const int sg = blockIdx.x * 2 + sub;
    const int nsg = gridDim.x * 2;

    for (int base = sg * 8; base < E; base += nsg * 8) {
        float2 v[8]; float w[8]; int cls[8];
        #pragma unroll
        for (int u = 0; u < 8; u++) {
            int e = base + u;
            uint2 d; const float2* p;
            if (e < M) {
                d = __ldg(&g_desc_src[e]);
                p = (const float2*)(sfeat + (size_t)(d.x >> 5) * DF);
            } else if (e < E) {
                d = __ldg(&g_desc_tgt[e - M]);
                p = (const float2*)(tfeat + (size_t)(e - M) * DF);
            } else {
                d = make_uint2(0u, 0u);
                p = (const float2*)tfeat;
            }
            cls[u] = (int)(d.x & 31u);
            w[u] = __uint_as_float(d.y);
            v[u] = __ldg(p + l);
        }
        #pragma unroll
        for (int u = 0; u < 8; u++) {
            int a = cls[u] * 128 + l;
            accx[sub][a] = fmaf(w[u], v[u].x, accx[sub][a]);
            accy[sub][a] = fmaf(w[u], v[u].y, accy[sub][a]);
        }
    }

    __syncthreads();
    for (int i = t; i < C * 128; i += 256) {
        int cls = i >> 7, ll = i & 127;
        atomicAdd(&g_sums[cls * DF + 2 * ll],     accx[0][i] + accx[1][i]);
        atomicAdd(&g_sums[cls * DF + 2 * ll + 1], accy[0][i] + accy[1][i]);
    }
}

// ---------------- K3: register-resident-centroid GEMM + entropy ----------------
// 8 compute warps (4 pairs; pair covers 2 entries; h=warp&1 covers half the dims,
// lane holds 5 classes x 4 float4 of centroids in registers) + 1 epilogue warp.
#define K3_THREADS 288
#define K3_GRID 148
#define BATCH 8

__device__ __forceinline__ const float4* k3_row_ptr(
    int e, int M, int E, const float* sfeat, const float* tfeat)
{
    if (e < M) {
        uint2 d = __ldg(&g_desc_src[e]);
        return (const float4*)(sfeat + (size_t)(d.x >> 5) * DF);
    }
    if (e < E) return (const float4*)(tfeat + (size_t)(e - M) * DF);
    return (const float4*)tfeat;
}

__global__ void __launch_bounds__(K3_THREADS) k3_entropy(
    const float* __restrict__ sfeat, const float* __restrict__ tfeat, int N)
{
    __shared__ float4 scent[C * 64];
    __shared__ float zsm[2][2][BATCH][CPAD];   // [buf][half][entry][class]
    __shared__ float bsum[K3_THREADS / 32];
    const int t = threadIdx.x;

    for (int i = t; i < C * 64; i += K3_THREADS) {
        float den = __ldg(&g_denom[i >> 6]);
        float inv = (den > 0.f) ? 1.f / fmaxf(den, 1e-12f) : 0.f;
        float4 s = ((const float4*)g_sums)[i];
        scent[i] = make_float4(s.x * inv, s.y * inv, s.z * inv, s.w * inv);
    }
    unsigned seen = 0;
    #pragma unroll
    for (int c = 0; c < C; c++) if (__ldg(&g_denom[c]) > 0.f) seen |= (1u << c);
    const int M = g_src_count;
    const int E = M + N;
    __syncthreads();

    const int warp = t >> 5, lane = t & 31;
    const int step = gridDim.x * BATCH;
    float partial = 0.f;

    if (warp < 8) {
        const int pair = warp >> 1, h = warp & 1;
        const int g = lane >> 3, sub = lane & 7;

        // centroid registers: 5 classes x 4 float4 (this lane's dim slice)
        F4U cw[5][4];
        #pragma unroll
        for (int cl = 0; cl < 5; cl++) {
            int c = g * 5 + cl;
            #pragma unroll
            for (int j = 0; j < 4; j++) {
                int q = h * 32 + j * 8 + sub;
                cw[cl][j].f = (c < C) ? scent[c * 64 + q] : make_float4(0.f, 0.f, 0.f, 0.f);
            }
        }

        F4U r[2][2][4];   // [buf][entry][j]
        const int b0 = blockIdx.x * BATCH;
        if (b0 < E) {
            #pragma unroll
            for (int i = 0; i < 2; i++) {
                const float4* rp = k3_row_ptr(b0 + pair * 2 + i, M, E, sfeat, tfeat);
                #pragma unroll
                for (int j = 0; j < 4; j++) r[0][i][j].f = __ldg(rp + h * 32 + j * 8 + sub);
            }
        }

        int buf = 0;
        for (int b = b0; b < E; b += step) {
            int nb = b + step;
            if (nb < E) {
                #pragma unroll
                for (int i = 0; i < 2; i++) {
                    const float4* rp = k3_row_ptr(nb + pair * 2 + i, M, E, sfeat, tfeat);
                    #pragma unroll
                    for (int j = 0; j < 4; j++) r[buf ^ 1][i][j].f = __ldg(rp + h * 32 + j * 8 + sub);
                }
            }

            ull acc[2][5];
            #pragma unroll
            for (int i = 0; i < 2; i++)
                #pragma unroll
                for (int cl = 0; cl < 5; cl++) acc[i][cl] = 0ull;

            #pragma unroll
            for (int j = 0; j < 4; j++) {
                #pragma unroll
                for (int cl = 0; cl < 5; cl++) {
                    fma2(acc[0][cl], r[buf][0][j].u.x, cw[cl][j].u.x);
                    fma2(acc[0][cl], r[buf][0][j].u.y, cw[cl][j].u.y);
                    fma2(acc[1][cl], r[buf][1][j].u.x, cw[cl][j].u.x);
                    fma2(acc[1][cl], r[buf][1][j].u.y, cw[cl][j].u.y);
                }
            }

            // collapse f32x2 + butterfly over sub lanes (xor 1,2,4)
            #pragma unroll
            for (int i = 0; i < 2; i++) {
                #pragma unroll
                for (int cl = 0; cl < 5; cl++) {
                    U2F u; u.u = acc[i][cl];
                    float s = u.f.x + u.f.y;
                    s += __shfl_xor_sync(0xffffffffu, s, 1);
                    s += __shfl_xor_sync(0xffffffffu, s, 2);
                    s += __shfl_xor_sync(0xffffffffu, s, 4);
                    if (sub == 0) zsm[buf][h][pair * 2 + i][g * 5 + cl] = s;
                }
            }
            __syncthreads();
            buf ^= 1;
        }
    } else {
        // epilogue warp: entropy over the z-tile written last iteration
        int buf = 0;
        for (int b = blockIdx.x * BATCH; b < E; b += step) {
            __syncthreads();
            if (lane < BATCH) {
                int e = b + lane;
                float w = 0.f;
                if (e < M) w = 1.f;
                else if (e < E) w = __uint_as_float(__ldg(&g_desc_tgt[e - M]).y);

                float z[C];
                #pragma unroll
                for (int c = 0; c < C; c++) z[c] = zsm[buf][0][lane][c] + zsm[buf][1][lane][c];
                float m = -3.4e38f;
                #pragma unroll
                for (int c = 0; c < C; c++) if ((seen >> c) & 1u) m = fmaxf(m, z[c]);
                float S = 0.f, U = 0.f;
                #pragma unroll
                for (int c = 0; c < C; c++) if ((seen >> c) & 1u) {
                    float ex = __expf(z[c] - m);
                    S += ex;
                    U = fmaf(z[c], ex, U);
                }
                float ent = U / S - m - __logf(S);
                partial += w * ent;
            }
            buf ^= 1;
        }
    }

    // block reduce (only epilogue warp has nonzero partial, but reduce all)
    #pragma unroll
    for (int o = 16; o; o >>= 1) partial += __shfl_down_sync(0xffffffffu, partial, o);
    if (lane == 0) bsum[warp] = partial;
    __syncthreads();
    if (t == 0) {
        float s = 0.f;
        #pragma unroll
        for (int wp = 0; wp < K3_THREADS / 32; wp++) s += bsum[wp];
        atomicAdd(&g_total, (double)s);
    }
}

// ---------------- K2: write centroid block of the output ----------------
__global__ void k2_centroids(float* __restrict__ out) {
    int c = blockIdx.x, d = threadIdx.x;
    float den = g_denom[c];
    bool seen = den > 0.f;
    float s = g_sums[c * DF + d];
    out[c * DF + d] = seen ? s / fmaxf(den, 1e-12f) : __int_as_float(0x7f800000);
}

// ---------------- K4: finalize loss ----------------
__global__ void k4_final(float* __restrict__ out, int N) {
    out[C * DF] = (float)(-(g_total / (g_ws + (double)N)));
}

// ---------------- launch ----------------
extern "C" void kernel_launch(void* const* d_in, const int* in_sizes, int n_in,
                              void* d_out, int out_size) {
    const float* sfeat = (const float*)d_in[0];
    const float* tfeat = (const float*)d_in[1];
    const float* conf  = (const float*)d_in[2];
    const int*   sarg  = (const int*)d_in[3];
    const int*   targ  = (const int*)d_in[4];
    const int*   smask = (const int*)d_in[5];
    float* out = (float*)d_out;
    int N = in_sizes[2];   // target_conf element count = N_PIX

    k0_zero<<<1, 256>>>();
    k1a_meta<<<K1A_BLOCKS, 256>>>(conf, sarg, targ, smask, N);
    k1b_sums<<<K1B_BLOCKS, 256>>>(sfeat, tfeat, N);
    k3_entropy<<<K3_GRID, K3_THREADS>>>(sfeat, tfeat, N);   // capture index 3
    k2_centroids<<<C, DF>>>(out);
    k4_final<<<1, 1>>>(out, N);
}

// round 6
// speedup vs baseline: 2.8649x; 2.8649x over previous
#include <cuda_runtime.h>
#include <cstdint>

#define C 19
#define DF 256
#define NPIX_MAX 262144

// ---------------- scratch (device globals; no runtime allocation) ----------------
__device__ float g_sums[C * DF];
__device__ float g_denom[C];
__device__ int g_src_count;
__device__ uint2 g_desc_src[NPIX_MAX];   // {row<<5 | cls, bits(w=1)}
__device__ uint2 g_desc_tgt[NPIX_MAX];   // {row<<5 | cls, bits(1-conf)}
__device__ double g_total;
__device__ double g_ws;

typedef unsigned long long ull;

union F4U { float4 f; ulonglong2 u; };
union U2F { ull u; float2 f; };

__device__ __forceinline__ void fma2(ull& d, ull a, ull b) {
    asm("fma.rn.f32x2 %0, %1, %2, %0;" : "+l"(d) : "l"(a), "l"(b));
}

// ---------------- K0: zero scratch (must run every replay) ----------------
__global__ void k0_zero() {
    int t = threadIdx.x;
    for (int i = t; i < C * DF; i += 256) g_sums[i] = 0.f;
    if (t < C) g_denom[t] = 0.f;
    if (t == 0) { g_total = 0.0; g_ws = 0.0; g_src_count = 0; }
}

// ---------------- K1a: denoms + ws + entry descriptors ----------------
#define K1A_BLOCKS 512
__global__ void __launch_bounds__(256) k1a_meta(
    const float* __restrict__ conf, const int* __restrict__ sarg,
    const int* __restrict__ targ, const int* __restrict__ smask, int N)
{
    __shared__ float sden[C];
    __shared__ float swsum[8];
    const int t = threadIdx.x;
    if (t < C) sden[t] = 0.f;
    float wsl = 0.f;
    __syncthreads();

    const int stride = gridDim.x * blockDim.x;
    const int iters = (N + stride - 1) / stride;
    for (int it = 0; it < iters; it++) {
        int i = it * stride + blockIdx.x * blockDim.x + t;
        int flag = 0, cs = 0;
        if (i < N) {
            flag = (smask[i] != 0);
            cs = sarg[i];
            int ct = targ[i];
            float w = 1.f - conf[i];
            if (flag) { atomicAdd(&sden[cs], 1.f); wsl += 1.f; }
            atomicAdd(&sden[ct], w);
            g_desc_tgt[i] = make_uint2(((unsigned)i << 5) | (unsigned)ct, __float_as_uint(w));
        }
        unsigned bal = __ballot_sync(0xffffffffu, flag);
        int cnt = __popc(bal);
        int bbase = 0;
        if ((t & 31) == 0 && cnt) bbase = atomicAdd(&g_src_count, cnt);
        bbase = __shfl_sync(0xffffffffu, bbase, 0);
        if (flag) {
            int rank = __popc(bal & ((1u << (t & 31)) - 1u));
            g_desc_src[bbase + rank] = make_uint2(((unsigned)i << 5) | (unsigned)cs, __float_as_uint(1.f));
        }
    }

    __syncthreads();
    if (t < C) atomicAdd(&g_denom[t], sden[t]);
    #pragma unroll
    for (int o = 16; o; o >>= 1) wsl += __shfl_down_sync(0xffffffffu, wsl, o);
    if ((t & 31) == 0) swsum[t >> 5] = wsl;
    __syncthreads();
    if (t == 0) {
        float s = 0.f;
        #pragma unroll
        for (int w = 0; w < 8; w++) s += swsum[w];
        atomicAdd(&g_ws, (double)s);
    }
}

// ---------------- K1b: streaming per-class feature sums (R4 float2 version) ----
#define K1B_BLOCKS 740
__global__ void __launch_bounds__(256) k1b_sums(
    const float* __restrict__ sfeat, const float* __restrict__ tfeat, int N)
{
    __shared__ float acc[2][C * DF];   // one copy per 128-thread subgroup
    const int t = threadIdx.x;
    const int sub = t >> 7;            // 0 or 1
    const int l = t & 127;             // dim pair owner: dims [2l, 2l+1]

    for (int i = t; i < 2 * C * DF; i += 256) ((float*)acc)[i] = 0.f;
    __syncthreads();

    const int M = g_src_count;
    const int E = M + N;
    const int sg = blockIdx.x * 2 + sub;
    const int nsg = gridDim.x * 2;

    for (int base = sg * 8; base < E; base += nsg * 8) {
        float2 v[8]; float w[8]; int cls[8];
        #pragma unroll
        for (int u = 0; u < 8; u++) {
            int e = base + u;
            uint2 d; const float2* p;
            if (e < M) {
                d = __ldg(&g_desc_src[e]);
                p = (const float2*)(sfeat + (size_t)(d.x >> 5) * DF);
            } else if (e < E) {
                d = __ldg(&g_desc_tgt[e - M]);
                p = (const float2*)(tfeat + (size_t)(e - M) * DF);
            } else {
                d = make_uint2(0u, 0u);
                p = (const float2*)tfeat;
            }
            cls[u] = (int)(d.x & 31u);
            w[u] = __uint_as_float(d.y);
            v[u] = __ldg(p + l);
        }
        #pragma unroll
        for (int u = 0; u < 8; u++) {
            float2* a = (float2*)&acc[sub][cls[u] * DF + 2 * l];
            float2 av = *a;
            av.x = fmaf(w[u], v[u].x, av.x);
            av.y = fmaf(w[u], v[u].y, av.y);
            *a = av;
        }
    }

    __syncthreads();
    for (int i = t; i < C * DF; i += 256)
        atomicAdd(&g_sums[i], acc[0][i] + acc[1][i]);
}

// ---------------- K3: GEMM + entropy; 2 entries per 8-lane group, chunked ------
#define K3_GRID 148

__device__ __forceinline__ const float4* k3_row_ptr(
    int e, int M, int E, const float* sfeat, const float* tfeat)
{
    if (e < M) {
        uint2 d = __ldg(&g_desc_src[e]);
        return (const float4*)(sfeat + (size_t)(d.x >> 5) * DF);
    }
    if (e < E) return (const float4*)(tfeat + (size_t)(e - M) * DF);
    return (const float4*)tfeat;
}

__global__ void __launch_bounds__(256, 1) k3_entropy(
    const float* __restrict__ sfeat, const float* __restrict__ tfeat, int N)
{
    __shared__ float4 scent[C * 64];
    __shared__ float bsum[8];
    const int t = threadIdx.x;

    // block-local centroid computation (zero for unseen classes)
    for (int i = t; i < C * 64; i += 256) {
        float den = __ldg(&g_denom[i >> 6]);
        float inv = (den > 0.f) ? 1.f / fmaxf(den, 1e-12f) : 0.f;
        float4 s = ((const float4*)g_sums)[i];
        scent[i] = make_float4(s.x * inv, s.y * inv, s.z * inv, s.w * inv);
    }
    unsigned seen = 0;
    #pragma unroll
    for (int c = 0; c < C; c++) if (__ldg(&g_denom[c]) > 0.f) seen |= (1u << c);
    const int M = g_src_count;
    const int E = M + N;
    __syncthreads();

    const int warp = t >> 5, lane = t & 31;
    const int g = lane >> 3, sub = lane & 7;   // 8-lane groups
    const int eoff = warp * 8 + g * 2;         // CTA-iter covers 64 entries
    const int step = gridDim.x * 64;
    float partial = 0.f;

    F4U r[2][2][4];   // [chunk-buffer][entry][j2]; chunk kk covers float4s (kk*4+j2)*8+sub
    const int b0 = blockIdx.x * 64;

    // prefetch chunk 0 of first iteration
    if (b0 < E) {
        #pragma unroll
        for (int i = 0; i < 2; i++) {
            const float4* rp = k3_row_ptr(b0 + eoff + i, M, E, sfeat, tfeat);
            #pragma unroll
            for (int j2 = 0; j2 < 4; j2++) r[0][i][j2].f = __ldg(rp + j2 * 8 + sub);
        }
    }

    for (int base = b0; base < E; base += step) {
        const int e0 = base + eoff;

        // weights for the two entries
        float w[2];
        #pragma unroll
        for (int i = 0; i < 2; i++) {
            int e = e0 + i;
            if (e < M) w[i] = 1.f;
            else if (e < E) w[i] = __uint_as_float(__ldg(&g_desc_tgt[e - M]).y);
            else w[i] = 0.f;
        }

        // load chunk 1 of this iteration
        #pragma unroll
        for (int i = 0; i < 2; i++) {
            const float4* rp = k3_row_ptr(e0 + i, M, E, sfeat, tfeat);
            #pragma unroll
            for (int j2 = 0; j2 < 4; j2++) r[1][i][j2].f = __ldg(rp + (4 + j2) * 8 + sub);
        }

        ull acc0[C], acc1[C];
        #pragma unroll
        for (int c = 0; c < C; c++) { acc0[c] = 0ull; acc1[c] = 0ull; }

        // compute chunk 0
        #pragma unroll
        for (int j2 = 0; j2 < 4; j2++) {
            const int q = j2 * 8 + sub;
            #pragma unroll
            for (int c = 0; c < C; c++) {
                F4U cc; cc.f = scent[c * 64 + q];
                fma2(acc0[c], r[0][0][j2].u.x, cc.u.x);
                fma2(acc1[c], r[0][1][j2].u.x, cc.u.x);
                fma2(acc0[c], r[0][0][j2].u.y, cc.u.y);
                fma2(acc1[c], r[0][1][j2].u.y, cc.u.y);
            }
        }

        // prefetch chunk 0 of next iteration
        const int nb = base + step;
        if (nb < E) {
            #pragma unroll
            for (int i = 0; i < 2; i++) {
                const float4* rp = k3_row_ptr(nb + eoff + i, M, E, sfeat, tfeat);
                #pragma unroll
                for (int j2 = 0; j2 < 4; j2++) r[0][i][j2].f = __ldg(rp + j2 * 8 + sub);
            }
        }

        // compute chunk 1
        #pragma unroll
        for (int j2 = 0; j2 < 4; j2++) {
            const int q = (4 + j2) * 8 + sub;
            #pragma unroll
            for (int c = 0; c < C; c++) {
                F4U cc; cc.f = scent[c * 64 + q];
                fma2(acc0[c], r[1][0][j2].u.x, cc.u.x);
                fma2(acc1[c], r[1][1][j2].u.x, cc.u.x);
                fma2(acc0[c], r[1][0][j2].u.y, cc.u.y);
                fma2(acc1[c], r[1][1][j2].u.y, cc.u.y);
            }
        }

        // reduce across sub lanes and compute entropy for both entries
        #pragma unroll
        for (int i = 0; i < 2; i++) {
            float z[C];
            #pragma unroll
            for (int c = 0; c < C; c++) {
                U2F u; u.u = (i == 0) ? acc0[c] : acc1[c];
                float s = u.f.x + u.f.y;
                s += __shfl_xor_sync(0xffffffffu, s, 1);
                s += __shfl_xor_sync(0xffffffffu, s, 2);
                s += __shfl_xor_sync(0xffffffffu, s, 4);
                z[c] = s;
            }
            float m = -3.4e38f;
            #pragma unroll
            for (int c = 0; c < C; c++) if ((seen >> c) & 1u) m = fmaxf(m, z[c]);
            float S = 0.f, U = 0.f;
            #pragma unroll
            for (int c = 0; c < C; c++) if ((seen >> c) & 1u) {
                float ex = __expf(z[c] - m);
                S += ex;
                U = fmaf(z[c], ex, U);
            }
            float ent = U / S - m - __logf(S);   // = sum_c p*logp over seen classes
            if (sub == 0) partial += w[i] * ent;
        }
    }

    #pragma unroll
    for (int o = 16; o; o >>= 1) partial += __shfl_down_sync(0xffffffffu, partial, o);
    if (lane == 0) bsum[warp] = partial;
    __syncthreads();
    if (t == 0) {
        float s = 0.f;
        #pragma unroll
        for (int wp = 0; wp < 8; wp++) s += bsum[wp];
        atomicAdd(&g_total, (double)s);
    }
}

// ---------------- K2: write centroid block of the output ----------------
__global__ void k2_centroids(float* __restrict__ out) {
    int c = blockIdx.x, d = threadIdx.x;
    float den = g_denom[c];
    bool seen = den > 0.f;
    float s = g_sums[c * DF + d];
    out[c * DF + d] = seen ? s / fmaxf(den, 1e-12f) : __int_as_float(0x7f800000);
}

// ---------------- K4: finalize loss ----------------
__global__ void k4_final(float* __restrict__ out, int N) {
    out[C * DF] = (float)(-(g_total / (g_ws + (double)N)));
}

// ---------------- launch ----------------
extern "C" void kernel_launch(void* const* d_in, const int* in_sizes, int n_in,
                              void* d_out, int out_size) {
    const float* sfeat = (const float*)d_in[0];
    const float* tfeat = (const float*)d_in[1];
    const float* conf  = (const float*)d_in[2];
    const int*   sarg  = (const int*)d_in[3];
    const int*   targ  = (const int*)d_in[4];
    const int*   smask = (const int*)d_in[5];
    float* out = (float*)d_out;
    int N = in_sizes[2];   // target_conf element count = N_PIX

    k0_zero<<<1, 256>>>();
    k1a_meta<<<K1A_BLOCKS, 256>>>(conf, sarg, targ, smask, N);
    k1b_sums<<<K1B_BLOCKS, 256>>>(sfeat, tfeat, N);
    k3_entropy<<<K3_GRID, 256>>>(sfeat, tfeat, N);   // capture index 3
    k2_centroids<<<C, DF>>>(out);
    k4_final<<<1, 1>>>(out, N);
}

// round 7
// speedup vs baseline: 3.3667x; 1.1751x over previous
#include <cuda_runtime.h>
#include <cstdint>

#define C 19
#define DF 256
#define NPIX_MAX 262144

// ---------------- scratch (device globals; no runtime allocation) ----------------
__device__ float g_sums[C * DF];
__device__ float g_denom[C];
__device__ int g_src_count;
__device__ uint2 g_desc_src[NPIX_MAX];   // {row<<5 | cls, bits(w=1)}
__device__ uint2 g_desc_tgt[NPIX_MAX];   // {row<<5 | cls, bits(1-conf)}
__device__ double g_total;
__device__ double g_ws;

typedef unsigned long long ull;

union F4U { float4 f; ulonglong2 u; };
union U2F { ull u; float2 f; };

__device__ __forceinline__ void fma2(ull& d, ull a, ull b) {
    asm("fma.rn.f32x2 %0, %1, %2, %0;" : "+l"(d) : "l"(a), "l"(b));
}

// ---------------- K0: zero scratch (must run every replay) ----------------
__global__ void k0_zero() {
    int t = threadIdx.x;
    for (int i = t; i < C * DF; i += 256) g_sums[i] = 0.f;
    if (t < C) g_denom[t] = 0.f;
    if (t == 0) { g_total = 0.0; g_ws = 0.0; g_src_count = 0; }
}

// ---------------- K1a: denoms + ws + entry descriptors ----------------
#define K1A_BLOCKS 512
__global__ void __launch_bounds__(256) k1a_meta(
    const float* __restrict__ conf, const int* __restrict__ sarg,
    const int* __restrict__ targ, const int* __restrict__ smask, int N)
{
    __shared__ float sden[C];
    __shared__ float swsum[8];
    const int t = threadIdx.x;
    if (t < C) sden[t] = 0.f;
    float wsl = 0.f;
    __syncthreads();

    const int stride = gridDim.x * blockDim.x;
    const int iters = (N + stride - 1) / stride;
    for (int it = 0; it < iters; it++) {
        int i = it * stride + blockIdx.x * blockDim.x + t;
        int flag = 0, cs = 0;
        if (i < N) {
            flag = (smask[i] != 0);
            cs = sarg[i];
            int ct = targ[i];
            float w = 1.f - conf[i];
            if (flag) { atomicAdd(&sden[cs], 1.f); wsl += 1.f; }
            atomicAdd(&sden[ct], w);
            g_desc_tgt[i] = make_uint2(((unsigned)i << 5) | (unsigned)ct, __float_as_uint(w));
        }
        unsigned bal = __ballot_sync(0xffffffffu, flag);
        int cnt = __popc(bal);
        int bbase = 0;
        if ((t & 31) == 0 && cnt) bbase = atomicAdd(&g_src_count, cnt);
        bbase = __shfl_sync(0xffffffffu, bbase, 0);
        if (flag) {
            int rank = __popc(bal & ((1u << (t & 31)) - 1u));
            g_desc_src[bbase + rank] = make_uint2(((unsigned)i << 5) | (unsigned)cs, __float_as_uint(1.f));
        }
    }

    __syncthreads();
    if (t < C) atomicAdd(&g_denom[t], sden[t]);
    #pragma unroll
    for (int o = 16; o; o >>= 1) wsl += __shfl_down_sync(0xffffffffu, wsl, o);
    if ((t & 31) == 0) swsum[t >> 5] = wsl;
    __syncthreads();
    if (t == 0) {
        float s = 0.f;
        #pragma unroll
        for (int w = 0; w < 8; w++) s += swsum[w];
        atomicAdd(&g_ws, (double)s);
    }
}

// ---------------- K1b: streaming per-class feature sums ----
#define K1B_BLOCKS 740
__global__ void __launch_bounds__(256) k1b_sums(
    const float* __restrict__ sfeat, const float* __restrict__ tfeat, int N)
{
    __shared__ float acc[2][C * DF];   // one copy per 128-thread subgroup
    const int t = threadIdx.x;
    const int sub = t >> 7;            // 0 or 1
    const int l = t & 127;             // dim pair owner: dims [2l, 2l+1]

    for (int i = t; i < 2 * C * DF; i += 256) ((float*)acc)[i] = 0.f;
    __syncthreads();

    const int M = g_src_count;
    const int E = M + N;
    const int sg = blockIdx.x * 2 + sub;
    const int nsg = gridDim.x * 2;

    for (int base = sg * 8; base < E; base += nsg * 8) {
        float2 v[8]; float w[8]; int cls[8];
        #pragma unroll
        for (int u = 0; u < 8; u++) {
            int e = base + u;
            uint2 d; const float2* p;
            if (e < M) {
                d = __ldg(&g_desc_src[e]);
                p = (const float2*)(sfeat + (size_t)(d.x >> 5) * DF);
            } else if (e < E) {
                d = __ldg(&g_desc_tgt[e - M]);
                p = (const float2*)(tfeat + (size_t)(e - M) * DF);
            } else {
                d = make_uint2(0u, 0u);
                p = (const float2*)tfeat;
            }
            cls[u] = (int)(d.x & 31u);
            w[u] = __uint_as_float(d.y);
            v[u] = __ldg(p + l);
        }
        #pragma unroll
        for (int u = 0; u < 8; u++) {
            float2* a = (float2*)&acc[sub][cls[u] * DF + 2 * l];
            float2 av = *a;
            av.x = fmaf(w[u], v[u].x, av.x);
            av.y = fmaf(w[u], v[u].y, av.y);
            *a = av;
        }
    }

    __syncthreads();
    for (int i = t; i < C * DF; i += 256)
        atomicAdd(&g_sums[i], acc[0][i] + acc[1][i]);
}

// ---------------- K3: GEMM + entropy; 192 threads, 2 CTAs/SM ------
#define K3_THREADS 192
#define K3_GRID 296
#define K3_PER_BLOCK 48    // 6 warps * 8 entries

__device__ __forceinline__ const float4* k3_row_ptr(
    int e, int M, int E, const float* sfeat, const float* tfeat)
{
    if (e < M) {
        uint2 d = __ldg(&g_desc_src[e]);
        return (const float4*)(sfeat + (size_t)(d.x >> 5) * DF);
    }
    if (e < E) return (const float4*)(tfeat + (size_t)(e - M) * DF);
    return (const float4*)tfeat;
}

__global__ void __launch_bounds__(K3_THREADS, 2) k3_entropy(
    const float* __restrict__ sfeat, const float* __restrict__ tfeat, int N)
{
    __shared__ float4 scent[C * 64];
    __shared__ float bsum[K3_THREADS / 32];
    const int t = threadIdx.x;

    // block-local centroid computation (zero for unseen classes)
    for (int i = t; i < C * 64; i += K3_THREADS) {
        float den = __ldg(&g_denom[i >> 6]);
        float inv = (den > 0.f) ? 1.f / fmaxf(den, 1e-12f) : 0.f;
        float4 s = ((const float4*)g_sums)[i];
        scent[i] = make_float4(s.x * inv, s.y * inv, s.z * inv, s.w * inv);
    }
    unsigned seen = 0;
    #pragma unroll
    for (int c = 0; c < C; c++) if (__ldg(&g_denom[c]) > 0.f) seen |= (1u << c);
    const int M = g_src_count;
    const int E = M + N;
    __syncthreads();

    const int warp = t >> 5, lane = t & 31;
    const int g = lane >> 3, sub = lane & 7;   // 8-lane groups
    const int eoff = warp * 8 + g * 2;         // CTA-iter covers 48 entries
    const int step = gridDim.x * K3_PER_BLOCK;
    float partial = 0.f;

    for (int base = blockIdx.x * K3_PER_BLOCK; base < E; base += step) {
        const int e0 = base + eoff;

        // weights + row pointers for the two entries
        float w[2]; const float4* rp[2];
        #pragma unroll
        for (int i = 0; i < 2; i++) {
            int e = e0 + i;
            rp[i] = k3_row_ptr(e, M, E, sfeat, tfeat);
            if (e < M) w[i] = 1.f;
            else if (e < E) w[i] = __uint_as_float(__ldg(&g_desc_tgt[e - M]).y);
            else w[i] = 0.f;
        }

        ull acc0[C], acc1[C];
        #pragma unroll
        for (int c = 0; c < C; c++) { acc0[c] = 0ull; acc1[c] = 0ull; }

        // two chunks of 4 float4s per lane; one chunk of rows live at a time
        #pragma unroll
        for (int kk = 0; kk < 2; kk++) {
            F4U r[2][4];
            #pragma unroll
            for (int i = 0; i < 2; i++)
                #pragma unroll
                for (int j2 = 0; j2 < 4; j2++)
                    r[i][j2].f = __ldg(rp[i] + (kk * 4 + j2) * 8 + sub);

            #pragma unroll
            for (int j2 = 0; j2 < 4; j2++) {
                const int q = (kk * 4 + j2) * 8 + sub;
                #pragma unroll
                for (int c = 0; c < C; c++) {
                    F4U cc; cc.f = scent[c * 64 + q];
                    fma2(acc0[c], r[0][j2].u.x, cc.u.x);
                    fma2(acc1[c], r[1][j2].u.x, cc.u.x);
                    fma2(acc0[c], r[0][j2].u.y, cc.u.y);
                    fma2(acc1[c], r[1][j2].u.y, cc.u.y);
                }
            }
        }

        // reduce across sub lanes and compute entropy for both entries
        #pragma unroll
        for (int i = 0; i < 2; i++) {
            float z[C];
            #pragma unroll
            for (int c = 0; c < C; c++) {
                U2F u; u.u = (i == 0) ? acc0[c] : acc1[c];
                float s = u.f.x + u.f.y;
                s += __shfl_xor_sync(0xffffffffu, s, 1);
                s += __shfl_xor_sync(0xffffffffu, s, 2);
                s += __shfl_xor_sync(0xffffffffu, s, 4);
                z[c] = s;
            }
            float m = -3.4e38f;
            #pragma unroll
            for (int c = 0; c < C; c++) if ((seen >> c) & 1u) m = fmaxf(m, z[c]);
            float S = 0.f, U = 0.f;
            #pragma unroll
            for (int c = 0; c < C; c++) if ((seen >> c) & 1u) {
                float ex = __expf(z[c] - m);
                S += ex;
                U = fmaf(z[c], ex, U);
            }
            float ent = U / S - m - __logf(S);   // = sum_c p*logp over seen classes
            if (sub == 0) partial += w[i] * ent;
        }
    }

    #pragma unroll
    for (int o = 16; o; o >>= 1) partial += __shfl_down_sync(0xffffffffu, partial, o);
    if (lane == 0) bsum[warp] = partial;
    __syncthreads();
    if (t == 0) {
        float s = 0.f;
        #pragma unroll
        for (int wp = 0; wp < K3_THREADS / 32; wp++) s += bsum[wp];
        atomicAdd(&g_total, (double)s);
    }
}

// ---------------- K2: write centroid block of the output ----------------
__global__ void k2_centroids(float* __restrict__ out) {
    int c = blockIdx.x, d = threadIdx.x;
    float den = g_denom[c];
    bool seen = den > 0.f;
    float s = g_sums[c * DF + d];
    out[c * DF + d] = seen ? s / fmaxf(den, 1e-12f) : __int_as_float(0x7f800000);
}

// ---------------- K4: finalize loss ----------------
__global__ void k4_final(float* __restrict__ out, int N) {
    out[C * DF] = (float)(-(g_total / (g_ws + (double)N)));
}

// ---------------- launch ----------------
extern "C" void kernel_launch(void* const* d_in, const int* in_sizes, int n_in,
                              void* d_out, int out_size) {
    const float* sfeat = (const float*)d_in[0];
    const float* tfeat = (const float*)d_in[1];
    const float* conf  = (const float*)d_in[2];
    const int*   sarg  = (const int*)d_in[3];
    const int*   targ  = (const int*)d_in[4];
    const int*   smask = (const int*)d_in[5];
    float* out = (float*)d_out;
    int N = in_sizes[2];   // target_conf element count = N_PIX

    k0_zero<<<1, 256>>>();
    k1a_meta<<<K1A_BLOCKS, 256>>>(conf, sarg, targ, smask, N);
    k1b_sums<<<K1B_BLOCKS, 256>>>(sfeat, tfeat, N);
    k3_entropy<<<K3_GRID, K3_THREADS>>>(sfeat, tfeat, N);   // capture index 3
    k2_centroids<<<C, DF>>>(out);
    k4_final<<<1, 1>>>(out, N);
}